// round 8
// baseline (speedup 1.0000x reference)
#include <cuda_runtime.h>
#include <cuda_fp16.h>
#include <cstdint>

// Dynamic-K sparse linear, fixed shape: x[16384,4096] * W[4096,4096]^T + bias.
//  1) k_transpose: WTh[c][o] = fp16_rn(W[o][c])  (32 MB scratch, K-major rows)
//     fp16 mantissa == tf32 mantissa (11 bits) -> precision-neutral vs tf32 W.
//  2) k_prescan:   per 64-row tile: active-channel idx list + compacted tf32 x
//  3) k_gemm:      64x256 tiles, 256 thr, 2+ CTAs/SM, 2-stage cp.async,
//                  A fp32 (padded), B fp16 (XOR-swizzled), tf32 mma.sync.

#define THRESH   1e-6f
#define CIN      4096
#define COUT     4096
#define NROWS    16384
#define TROWS    64
#define NTILES   (NROWS / TROWS)
#define KMAX     2048

__device__ __half g_WTh[(size_t)CIN * COUT];    // 32 MB, K-major fp16
__device__ float  g_XC[(size_t)NROWS * KMAX];   // 134 MB
__device__ int    g_IDX[NTILES * KMAX];         // 2 MB
__device__ int    g_CNT[NTILES];

namespace { struct WarmInit { WarmInit() { void* p; cudaGetSymbolAddress(&p, g_CNT); } } s_warm; }

__device__ __forceinline__ float tf32r(float v) {
    uint32_t r;
    asm("cvt.rna.tf32.f32 %0, %1;" : "=r"(r) : "f"(v));
    return __uint_as_float(r);
}

#define CP16(dst, src) \
    asm volatile("cp.async.cg.shared.global [%0], [%1], 16;" :: "r"(dst), "l"(src) : "memory")
#define CP_COMMIT() asm volatile("cp.async.commit_group;" ::: "memory")
#define CP_WAIT1()  asm volatile("cp.async.wait_group 1;" ::: "memory")

__device__ __forceinline__ uint32_t smem_u32(const void* p) {
    uint32_t a;
    asm("{ .reg .u64 t; cvta.to.shared.u64 t, %1; cvt.u32.u64 %0, t; }" : "=r"(a) : "l"(p));
    return a;
}

__device__ __forceinline__ void mma_tf32(float* d, const uint32_t* a, const uint32_t* b) {
    asm volatile(
        "mma.sync.aligned.m16n8k8.row.col.f32.tf32.tf32.f32 "
        "{%0,%1,%2,%3}, {%4,%5,%6,%7}, {%8,%9}, {%0,%1,%2,%3};"
        : "+f"(d[0]), "+f"(d[1]), "+f"(d[2]), "+f"(d[3])
        : "r"(a[0]), "r"(a[1]), "r"(a[2]), "r"(a[3]), "r"(b[0]), "r"(b[1]));
}

// ================= kernel 1: W transpose + fp16 round =================
__global__ void __launch_bounds__(256)
k_transpose(const float* __restrict__ w)
{
    __shared__ float t[32][33];
    const int c0 = blockIdx.x * 32;
    const int o0 = blockIdx.y * 32;
    const int tx = threadIdx.x, ty = threadIdx.y;
    #pragma unroll
    for (int i = 0; i < 32; i += 8)
        t[ty + i][tx] = w[(size_t)(o0 + ty + i) * CIN + c0 + tx];
    __syncthreads();
    #pragma unroll
    for (int i = 0; i < 32; i += 8)
        g_WTh[(size_t)(c0 + ty + i) * COUT + o0 + tx] = __float2half_rn(t[tx][ty + i]);
}

// ============ kernel 2: per-tile prescan + deterministic compaction ============
__global__ void __launch_bounds__(512)
k_prescan(const float* __restrict__ x)
{
    __shared__ float srow[2][CIN];
    __shared__ int   sidx[KMAX];
    __shared__ int   s_wcnt[16], s_woff[16], s_base;

    const int t = blockIdx.x;
    const int tid = threadIdx.x;
    const int wid = tid >> 5, lane = tid & 31;
    const float* xb = x + (size_t)t * TROWS * CIN;

    float mx[8];
    #pragma unroll
    for (int ch = 0; ch < 8; ch++) mx[ch] = 0.0f;
    for (int r = 0; r < TROWS; r++) {
        const float* row = xb + (size_t)r * CIN;
        #pragma unroll
        for (int ch = 0; ch < 8; ch++)
            mx[ch] = fmaxf(mx[ch], fabsf(row[ch * 512 + tid]));
    }

    if (tid == 0) s_base = 0;
    __syncthreads();

    for (int ch = 0; ch < 8; ch++) {
        const bool act = mx[ch] > THRESH;
        const unsigned bal = __ballot_sync(0xffffffffu, act);
        if (lane == 0) s_wcnt[wid] = __popc(bal);
        __syncthreads();
        if (tid == 0) {
            int s = s_base;
            #pragma unroll
            for (int wv = 0; wv < 16; wv++) { s_woff[wv] = s; s += s_wcnt[wv]; }
            s_base = s;
        }
        __syncthreads();
        if (act) {
            int pos = s_woff[wid] + __popc(bal & ((1u << lane) - 1u));
            if (pos < KMAX) sidx[pos] = ch * 512 + tid;
        }
        __syncthreads();
    }

    int count = min(s_base, KMAX);
    int kp = min((count + 31) & ~31, KMAX);
    if (kp == 0) kp = 32;
    if (tid == 0) g_CNT[t] = kp;
    for (int p = count + tid; p < kp; p += 512) sidx[p] = 0;
    __syncthreads();
    for (int p = tid; p < kp; p += 512) g_IDX[t * KMAX + p] = sidx[p];

    // gather 2 rows at a time; float4 stores
    const int half = tid >> 8;
    const int htid = tid & 255;
    for (int r = 0; r < TROWS; r += 2) {
        const float4* src = reinterpret_cast<const float4*>(xb + (size_t)(r + half) * CIN);
        #pragma unroll
        for (int q = 0; q < 4; q++)
            reinterpret_cast<float4*>(srow[half])[htid + q * 256] = src[htid + q * 256];
        __syncthreads();
        float* dst = g_XC + (size_t)(t * TROWS + r + half) * KMAX;
        for (int p4 = htid * 4; p4 < kp; p4 += 1024) {
            float4 v;
            v.x = (p4 + 0 < count) ? tf32r(srow[half][sidx[p4 + 0]]) : 0.0f;
            v.y = (p4 + 1 < count) ? tf32r(srow[half][sidx[p4 + 1]]) : 0.0f;
            v.z = (p4 + 2 < count) ? tf32r(srow[half][sidx[p4 + 2]]) : 0.0f;
            v.w = (p4 + 3 < count) ? tf32r(srow[half][sidx[p4 + 3]]) : 0.0f;
            *reinterpret_cast<float4*>(dst + p4) = v;
        }
        __syncthreads();
    }
}

// ================= kernel 3: sparse-K tf32 GEMM (B in fp16) =================
// 64x256 CTA tile, 256 threads (8 warps of 32x64).
// A: fp32 [2][64][36] padded (frag banks 4g+c, conflict-free).
// B: fp16 [2][32][256], per-row 16B-chunk swizzle: chunk' = chunk ^ k.
//    Fragment LDS.16 banks = (chunk%8)*4 + g/2, g-parity shares word: conflict-free.
#define BM 64
#define BN 256
#define BK 32
#define GEMM_NTH 256
#define APAD 36
#define A_STAGE_F (BM * APAD)            // 2304 floats = 9216 B
#define B_STAGE_H (BK * BN)              // 8192 halves = 16384 B
#define SM_A_BYTES (2 * A_STAGE_F * 4)   // 18432
#define SM_B_OFF   SM_A_BYTES
#define SM_B_BYTES (2 * B_STAGE_H * 2)   // 32768
#define SM_IDX_OFF (SM_B_OFF + SM_B_BYTES)
#define GEMM_SMEM_B (SM_IDX_OFF + KMAX * 4)   // 59392 B

__global__ void __launch_bounds__(GEMM_NTH, 2)
k_gemm(const float* __restrict__ bias, float* __restrict__ y)
{
    extern __shared__ char smem[];
    float*  As   = reinterpret_cast<float*>(smem);
    __half* Bs   = reinterpret_cast<__half*>(smem + SM_B_OFF);
    int*    sidx = reinterpret_cast<int*>(smem + SM_IDX_OFF);
    const uint32_t as_u = smem_u32(As);
    const uint32_t bs_u = smem_u32(Bs);

    const int tid  = threadIdx.x;
    const int wid  = tid >> 5, lane = tid & 31;
    const int g = lane >> 2, c = lane & 3;
    const int wm = wid >> 2;          // 0..1 -> 32-row band
    const int wn = wid & 3;           // 0..3 -> 64-col band

    const int t  = blockIdx.y;
    const int bc = blockIdx.x * BN;

    const int Kp = __ldg(&g_CNT[t]);
    const int KITERS = Kp >> 5;

    for (int p = tid; p < KMAX; p += GEMM_NTH) sidx[p] = (p < Kp) ? g_IDX[t * KMAX + p] : 0;
    __syncthreads();

    float acc[2][8][4];
    #pragma unroll
    for (int i = 0; i < 2; i++)
        #pragma unroll
        for (int j = 0; j < 8; j++)
            #pragma unroll
            for (int q = 0; q < 4; q++) acc[i][j][q] = 0.0f;

    // A: 512 16B chunks/stage -> 2/thread. B: 1024 16B chunks -> 4/thread.
    const int a_row = tid >> 2, a_j = tid & 3;
    const int b_r = tid >> 3, b_jj = tid & 7;       // row 0..31, chunk base 0..7
    const float* a_src_base = g_XC + (size_t)(t * TROWS + a_row) * KMAX + a_j * 4;
    const uint32_t a_dst_base = as_u + (uint32_t)(a_row * APAD + a_j * 4) * 4u;

    auto load_stage = [&](int kt, int s) {
        const int k0 = kt * BK;
        CP16(a_dst_base + (uint32_t)(s * A_STAGE_F) * 4u, a_src_base + k0);
        CP16(a_dst_base + (uint32_t)(s * A_STAGE_F + 16) * 4u, a_src_base + k0 + 16);
        const int ch = sidx[k0 + b_r];
        const __half* bsrc = g_WTh + (size_t)ch * COUT + bc;
        const uint32_t brow = bs_u + (uint32_t)(s * B_STAGE_H + b_r * BN) * 2u;
        #pragma unroll
        for (int i = 0; i < 4; i++) {
            const int chunk = b_jj + 8 * i;                 // logical 16B chunk (8 halves)
            const int cs = chunk ^ b_r;                     // swizzled position
            CP16(brow + (uint32_t)cs * 16u, bsrc + chunk * 8);
        }
    };

    if (KITERS > 0) load_stage(0, 0);
    CP_COMMIT();
    if (KITERS > 1) load_stage(1, 1);
    CP_COMMIT();

    for (int kt = 0; kt < KITERS; kt++) {
        CP_WAIT1();
        __syncthreads();
        const int s = kt & 1;
        const float*  a_st = As + s * A_STAGE_F;
        const __half* b_st = Bs + s * B_STAGE_H;

        #pragma unroll
        for (int kk = 0; kk < 4; kk++) {
            uint32_t af[2][4], bf[8][2];
            #pragma unroll
            for (int i = 0; i < 2; i++) {
                const int rm = wm * 32 + i * 16;
                af[i][0] = __float_as_uint(a_st[(rm + g)     * APAD + kk * 8 + c]);
                af[i][1] = __float_as_uint(a_st[(rm + g + 8) * APAD + kk * 8 + c]);
                af[i][2] = __float_as_uint(a_st[(rm + g)     * APAD + kk * 8 + c + 4]);
                af[i][3] = __float_as_uint(a_st[(rm + g + 8) * APAD + kk * 8 + c + 4]);
            }
            const int k0 = kk * 8 + c;
            const int k1 = k0 + 4;
            #pragma unroll
            for (int j = 0; j < 8; j++) {
                const int chunk = wn * 8 + j;               // logical chunk holds 8 n (g index)
                const __half h0 = b_st[k0 * BN + (chunk ^ k0) * 8 + g];
                const __half h1 = b_st[k1 * BN + (chunk ^ k1) * 8 + g];
                bf[j][0] = __float_as_uint(__half2float(h0));
                bf[j][1] = __float_as_uint(__half2float(h1));
            }
            #pragma unroll
            for (int i = 0; i < 2; i++)
                #pragma unroll
                for (int j = 0; j < 8; j++)
                    mma_tf32(acc[i][j], af[i], bf[j]);
        }

        __syncthreads();
        if (kt + 2 < KITERS) load_stage(kt + 2, s);
        CP_COMMIT();
    }

    #pragma unroll
    for (int j = 0; j < 8; j++) {
        const int col = bc + wn * 64 + j * 8 + c * 2;
        const float bx = __ldg(bias + col);
        const float by = __ldg(bias + col + 1);
        #pragma unroll
        for (int i = 0; i < 2; i++) {
            const int row0 = t * TROWS + wm * 32 + i * 16 + g;
            float2 v0, v1;
            v0.x = acc[i][j][0] + bx;  v0.y = acc[i][j][1] + by;
            v1.x = acc[i][j][2] + bx;  v1.y = acc[i][j][3] + by;
            *reinterpret_cast<float2*>(y + (size_t)row0 * COUT + col) = v0;
            *reinterpret_cast<float2*>(y + (size_t)(row0 + 8) * COUT + col) = v1;
        }
    }
}

// ================= launcher =================
extern "C" void kernel_launch(void* const* d_in, const int* in_sizes, int n_in,
                              void* d_out, int out_size)
{
    const float* x    = (const float*)d_in[0];
    const float* w    = (const float*)d_in[1];
    const float* bias = (const float*)d_in[2];
    float* y = (float*)d_out;

    static int configured = 0;
    if (!configured) {
        cudaFuncSetAttribute(k_gemm, cudaFuncAttributeMaxDynamicSharedMemorySize, GEMM_SMEM_B);
        configured = 1;
    }

    k_transpose<<<dim3(CIN / 32, COUT / 32), dim3(32, 8)>>>(w);
    k_prescan<<<NTILES, 512>>>(x);
    k_gemm<<<dim3(COUT / BN, NTILES), GEMM_NTH, GEMM_SMEM_B>>>(bias, y);
}

// round 10
// speedup vs baseline: 1.8668x; 1.8668x over previous
#include <cuda_runtime.h>
#include <cuda_fp16.h>
#include <cstdint>

// Dynamic-K sparse linear, fixed shape: x[16384,4096] * W[4096,4096]^T + bias.
//  1) k_transpose: WTh[c][o] = fp16_rn(W[o][c])   (32 MB, K-major rows)
//  2) k_prescan:   per 64-row tile: active-channel list + compacted fp16 x
//  3) k_gemm:      64x256 tiles, 256 thr, 2 CTAs/SM, 2-stage cp.async,
//                  fp16 operands via ldmatrix, mma.m16n8k16.f16.f16.f32.
// fp16 mantissa (11b) == tf32 mantissa; products exact, fp32 accumulate ->
// same error model as the tf32 path (~3e-4).

#define THRESH   1e-6f
#define CIN      4096
#define COUT     4096
#define NROWS    16384
#define TROWS    64
#define NTILES   (NROWS / TROWS)
#define KMAX     2048

__device__ __half g_WTh[(size_t)CIN * COUT];    // 32 MB, K-major fp16
__device__ __half g_XCh[(size_t)NROWS * KMAX];  // 67 MB, compacted fp16 x
__device__ int    g_IDX[NTILES * KMAX];
__device__ int    g_CNT[NTILES];

namespace { struct WarmInit { WarmInit() { void* p; cudaGetSymbolAddress(&p, g_CNT); } } s_warm; }

#define CP16(dst, src) \
    asm volatile("cp.async.cg.shared.global [%0], [%1], 16;" :: "r"(dst), "l"(src) : "memory")
#define CP_COMMIT() asm volatile("cp.async.commit_group;" ::: "memory")
#define CP_WAIT1()  asm volatile("cp.async.wait_group 1;" ::: "memory")

__device__ __forceinline__ uint32_t smem_u32(const void* p) {
    uint32_t a;
    asm("{ .reg .u64 t; cvta.to.shared.u64 t, %1; cvt.u32.u64 %0, t; }" : "=r"(a) : "l"(p));
    return a;
}

#define LDSM_X4(r0, r1, r2, r3, addr) \
    asm volatile("ldmatrix.sync.aligned.m8n8.x4.shared.b16 {%0,%1,%2,%3}, [%4];" \
        : "=r"(r0), "=r"(r1), "=r"(r2), "=r"(r3) : "r"(addr))
#define LDSM_X4_T(r0, r1, r2, r3, addr) \
    asm volatile("ldmatrix.sync.aligned.m8n8.x4.trans.shared.b16 {%0,%1,%2,%3}, [%4];" \
        : "=r"(r0), "=r"(r1), "=r"(r2), "=r"(r3) : "r"(addr))

__device__ __forceinline__ void mma_f16(float* d, const uint32_t* a, const uint32_t* b) {
    asm volatile(
        "mma.sync.aligned.m16n8k16.row.col.f32.f16.f16.f32 "
        "{%0,%1,%2,%3}, {%4,%5,%6,%7}, {%8,%9}, {%0,%1,%2,%3};"
        : "+f"(d[0]), "+f"(d[1]), "+f"(d[2]), "+f"(d[3])
        : "r"(a[0]), "r"(a[1]), "r"(a[2]), "r"(a[3]), "r"(b[0]), "r"(b[1]));
}

// ================= kernel 1: W transpose + fp16 round =================
__global__ void __launch_bounds__(256)
k_transpose(const float* __restrict__ w)
{
    __shared__ float t[32][33];
    const int c0 = blockIdx.x * 32;
    const int o0 = blockIdx.y * 32;
    const int tx = threadIdx.x, ty = threadIdx.y;
    #pragma unroll
    for (int i = 0; i < 32; i += 8)
        t[ty + i][tx] = w[(size_t)(o0 + ty + i) * CIN + c0 + tx];
    __syncthreads();
    #pragma unroll
    for (int i = 0; i < 32; i += 8)
        g_WTh[(size_t)(c0 + ty + i) * COUT + o0 + tx] = __float2half_rn(t[tx][ty + i]);
}

// ============ kernel 2: per-tile prescan + deterministic compaction ============
__global__ void __launch_bounds__(512)
k_prescan(const float* __restrict__ x)
{
    __shared__ float srow[2][CIN];
    __shared__ int   sidx[KMAX];
    __shared__ int   s_wcnt[16], s_woff[16], s_base;

    const int t = blockIdx.x;
    const int tid = threadIdx.x;
    const int wid = tid >> 5, lane = tid & 31;
    const float* xb = x + (size_t)t * TROWS * CIN;

    float mx[8];
    #pragma unroll
    for (int ch = 0; ch < 8; ch++) mx[ch] = 0.0f;
    for (int r = 0; r < TROWS; r++) {
        const float* row = xb + (size_t)r * CIN;
        #pragma unroll
        for (int ch = 0; ch < 8; ch++)
            mx[ch] = fmaxf(mx[ch], fabsf(row[ch * 512 + tid]));
    }

    if (tid == 0) s_base = 0;
    __syncthreads();

    for (int ch = 0; ch < 8; ch++) {
        const bool act = mx[ch] > THRESH;
        const unsigned bal = __ballot_sync(0xffffffffu, act);
        if (lane == 0) s_wcnt[wid] = __popc(bal);
        __syncthreads();
        if (tid == 0) {
            int s = s_base;
            #pragma unroll
            for (int wv = 0; wv < 16; wv++) { s_woff[wv] = s; s += s_wcnt[wv]; }
            s_base = s;
        }
        __syncthreads();
        if (act) {
            int pos = s_woff[wid] + __popc(bal & ((1u << lane) - 1u));
            if (pos < KMAX) sidx[pos] = ch * 512 + tid;
        }
        __syncthreads();
    }

    int count = min(s_base, KMAX);
    int kp = min((count + 31) & ~31, KMAX);
    if (kp == 0) kp = 32;
    if (tid == 0) g_CNT[t] = kp;
    for (int p = count + tid; p < kp; p += 512) sidx[p] = 0;
    __syncthreads();
    for (int p = tid; p < kp; p += 512) g_IDX[t * KMAX + p] = sidx[p];

    // gather 2 rows at a time, fp16 output, 16B packed stores (8 halves)
    const int half = tid >> 8;
    const int htid = tid & 255;
    for (int r = 0; r < TROWS; r += 2) {
        const float4* src = reinterpret_cast<const float4*>(xb + (size_t)(r + half) * CIN);
        #pragma unroll
        for (int q = 0; q < 4; q++)
            reinterpret_cast<float4*>(srow[half])[htid + q * 256] = src[htid + q * 256];
        __syncthreads();
        __half* dst = g_XCh + (size_t)(t * TROWS + r + half) * KMAX;
        for (int p8 = htid * 8; p8 < kp; p8 += 2048) {
            __half2 h[4];
            #pragma unroll
            for (int q = 0; q < 4; q++) {
                const int p = p8 + q * 2;
                float lo = (p     < count) ? srow[half][sidx[p]]     : 0.0f;
                float hi = (p + 1 < count) ? srow[half][sidx[p + 1]] : 0.0f;
                h[q] = __floats2half2_rn(lo, hi);
            }
            *reinterpret_cast<uint4*>(dst + p8) = *reinterpret_cast<uint4*>(h);
        }
        __syncthreads();
    }
}

// ================= kernel 3: sparse-K fp16 GEMM =================
// 64x256 CTA tile, 256 threads (8 warps of 32x64), 2 CTAs/SM, 2 stages.
// A: fp16 [2][64][40] halves (stride 80B = 5 x 16B units, 5 coprime 8 -> LDSM ok)
// B: fp16 [2][32][264] halves k-major (stride 528B = 33 units == 1 mod 8 -> ok)
#define BM 64
#define BN 256
#define BK 32
#define GEMM_NTH 256
#define AKP 40
#define BNP 264
#define A_STAGE_H (BM * AKP)             // 2560 halves = 5120 B
#define B_STAGE_H (BK * BNP)             // 8448 halves = 16896 B
#define SM_B_OFF  (2 * A_STAGE_H * 2)    // 10240
#define SM_IDX_OFF (SM_B_OFF + 2 * B_STAGE_H * 2)
#define GEMM_SMEM_B (SM_IDX_OFF + KMAX * 4)

__global__ void __launch_bounds__(GEMM_NTH, 2)
k_gemm(const float* __restrict__ bias, float* __restrict__ y)
{
    extern __shared__ char smem[];
    __half* As   = reinterpret_cast<__half*>(smem);
    __half* Bs   = reinterpret_cast<__half*>(smem + SM_B_OFF);
    int*    sidx = reinterpret_cast<int*>(smem + SM_IDX_OFF);
    const uint32_t as_u = smem_u32(As);
    const uint32_t bs_u = smem_u32(Bs);

    const int tid  = threadIdx.x;
    const int wid  = tid >> 5, lane = tid & 31;
    const int g = lane >> 2, c = lane & 3;
    const int wm = wid >> 2;          // 0..1 -> 32-row band
    const int wn = wid & 3;           // 0..3 -> 64-col band

    const int t  = blockIdx.y;
    const int bc = blockIdx.x * BN;

    const int Kp = __ldg(&g_CNT[t]);
    const int KITERS = Kp >> 5;

    for (int p = tid; p < KMAX; p += GEMM_NTH) sidx[p] = (p < Kp) ? g_IDX[t * KMAX + p] : 0;
    __syncthreads();

    float acc[2][8][4];
    #pragma unroll
    for (int i = 0; i < 2; i++)
        #pragma unroll
        for (int j = 0; j < 8; j++)
            #pragma unroll
            for (int q = 0; q < 4; q++) acc[i][j][q] = 0.0f;

    // ---- ldmatrix per-lane base addresses ----
    // A x4: m = lane/8, r = lane%8: row = wm*32 + (m&1)*8 + r, kbyte = (m>>1)*16
    const int a_m = lane >> 3, a_r = lane & 7;
    const uint32_t a_lm = as_u +
        (uint32_t)((wm * 32 + (a_m & 1) * 8 + a_r) * AKP) * 2u + (uint32_t)((a_m >> 1) * 16);
    // B x4.trans: k-row = (m&1)*8 + r, n-offset = wn*64 + (m>>1)*8
    const uint32_t b_lm = bs_u +
        (uint32_t)(((a_m & 1) * 8 + a_r) * BNP) * 2u + (uint32_t)((wn * 64 + (a_m >> 1) * 8) * 2);

    // ---- cp.async mappings ----
    // A: 256 chunks/stage -> 1/thread: row = tid>>2, 8 halves at 8*(tid&3)
    const int a_row = tid >> 2, a_j = tid & 3;
    const __half* a_src_base = g_XCh + (size_t)(t * TROWS + a_row) * KMAX + a_j * 8;
    const uint32_t a_dst = as_u + (uint32_t)(a_row * AKP + a_j * 8) * 2u;
    // B: 1024 chunks/stage -> 4/thread: k-row = tid>>3, chunks (tid&7) + 8i
    const int b_r = tid >> 3, b_jj = tid & 7;
    const uint32_t b_dst = bs_u + (uint32_t)(b_r * BNP) * 2u;

    auto load_stage = [&](int kt, int s) {
        const int k0 = kt * BK;
        CP16(a_dst + (uint32_t)(s * A_STAGE_H) * 2u, a_src_base + k0);
        const int ch = sidx[k0 + b_r];
        const __half* bsrc = g_WTh + (size_t)ch * COUT + bc;
        const uint32_t bd = b_dst + (uint32_t)(s * B_STAGE_H) * 2u;
        #pragma unroll
        for (int i = 0; i < 4; i++) {
            const int chunk = b_jj + 8 * i;
            CP16(bd + (uint32_t)chunk * 16u, bsrc + chunk * 8);
        }
    };

    if (KITERS > 0) load_stage(0, 0);
    CP_COMMIT();
    if (KITERS > 1) load_stage(1, 1);
    CP_COMMIT();

    for (int kt = 0; kt < KITERS; kt++) {
        CP_WAIT1();
        __syncthreads();
        const int s = kt & 1;
        const uint32_t a_st = a_lm + (uint32_t)(s * A_STAGE_H) * 2u;
        const uint32_t b_st = b_lm + (uint32_t)(s * B_STAGE_H) * 2u;

        #pragma unroll
        for (int kk = 0; kk < 2; kk++) {        // two k16 steps per BK=32
            uint32_t af[2][4], bf[8][2];
            const uint32_t a_k = a_st + (uint32_t)(kk * 16) * 2u;   // +16 halves
            #pragma unroll
            for (int i = 0; i < 2; i++)
                LDSM_X4(af[i][0], af[i][1], af[i][2], af[i][3],
                        a_k + (uint32_t)(i * 16 * AKP) * 2u);
            const uint32_t b_k = b_st + (uint32_t)(kk * 16 * BNP) * 2u;
            #pragma unroll
            for (int jp = 0; jp < 4; jp++)      // each x4.trans covers 2 j's
                LDSM_X4_T(bf[jp * 2][0], bf[jp * 2][1], bf[jp * 2 + 1][0], bf[jp * 2 + 1][1],
                          b_k + (uint32_t)(jp * 16) * 2u);
            #pragma unroll
            for (int i = 0; i < 2; i++)
                #pragma unroll
                for (int j = 0; j < 8; j++)
                    mma_f16(acc[i][j], af[i], bf[j]);
        }

        __syncthreads();
        if (kt + 2 < KITERS) load_stage(kt + 2, s);
        CP_COMMIT();
    }

    #pragma unroll
    for (int j = 0; j < 8; j++) {
        const int col = bc + wn * 64 + j * 8 + c * 2;
        const float bx = __ldg(bias + col);
        const float by = __ldg(bias + col + 1);
        #pragma unroll
        for (int i = 0; i < 2; i++) {
            const int row0 = t * TROWS + wm * 32 + i * 16 + g;
            float2 v0, v1;
            v0.x = acc[i][j][0] + bx;  v0.y = acc[i][j][1] + by;
            v1.x = acc[i][j][2] + bx;  v1.y = acc[i][j][3] + by;
            *reinterpret_cast<float2*>(y + (size_t)row0 * COUT + col) = v0;
            *reinterpret_cast<float2*>(y + (size_t)(row0 + 8) * COUT + col) = v1;
        }
    }
}

// ================= launcher =================
extern "C" void kernel_launch(void* const* d_in, const int* in_sizes, int n_in,
                              void* d_out, int out_size)
{
    const float* x    = (const float*)d_in[0];
    const float* w    = (const float*)d_in[1];
    const float* bias = (const float*)d_in[2];
    float* y = (float*)d_out;

    static int configured = 0;
    if (!configured) {
        cudaFuncSetAttribute(k_gemm, cudaFuncAttributeMaxDynamicSharedMemorySize, GEMM_SMEM_B);
        configured = 1;
    }

    k_transpose<<<dim3(CIN / 32, COUT / 32), dim3(32, 8)>>>(w);
    k_prescan<<<NTILES, 512>>>(x);
    k_gemm<<<dim3(COUT / BN, NTILES), GEMM_NTH, GEMM_SMEM_B>>>(bias, y);
}